// round 13
// baseline (speedup 1.0000x reference)
#include <cuda_runtime.h>
#include <cstdint>

#define HID      100
#define NREL     16
#define NBLK     5
#define CB       20
#define MAXN     100000
#define MAXRN    (NREL * MAXN)
#define MAXE     1600128      // >= ntiles*ETILE for E=1.6M
#define WSTRIDE  2004         // per-relation weight stride (2000 used + 4 pad)
#define ETILE    96
#define ETHREADS 480          // 15 warps: b = t/96 (0..4), warp-uniform

// ---------------- scratch (device globals; no allocations allowed) ----------------
// Invariant at kernel_launch entry (static init + k_cleanup/k_final maintain it):
// g_cnt, g_hist, g_chain all zero; g_edge[E..Epad) inert; g_agg all zero.
__device__ int   g_cnt[MAXRN];      // per-(rel,dst) edge counts
__device__ int   g_hist[MAXN];      // per-dst edge counts (for dst sort)
__device__ int   g_cursor[MAXN];    // scatter cursors (exclusive prefix)
__device__ int   g_chain[256];      // lookback-scan chain (0 = not ready)
__device__ int4  g_edge[MAXE];      // dst-sorted edges: {src, dst, rel, scale-bits}
__device__ float g_agg[MAXN * HID]; // edge-aggregation accumulator (zero at entry)
__device__ float g_h1[MAXN * HID];  // layer-1 output (post-relu)

// ---------------- helpers ----------------
__device__ __forceinline__ uint32_t smaddr(const void* p) {
    return (uint32_t)__cvta_generic_to_shared(p);
}
__device__ __forceinline__ void cpa16(uint32_t s, const void* g) {
    asm volatile("cp.async.cg.shared.global [%0], [%1], 16;" :: "r"(s), "l"(g));
}
#define CPA_COMMIT() asm volatile("cp.async.commit_group;" ::: "memory")
#define CPA_WAIT0()  asm volatile("cp.async.wait_group 0;" ::: "memory")

__device__ __forceinline__ void red_add_v4(float* gptr, float4 v) {
    asm volatile("red.global.add.v4.f32 [%0], {%1, %2, %3, %4};"
                 :: "l"(gptr), "f"(v.x), "f"(v.y), "f"(v.z), "f"(v.w) : "memory");
}

// ---------------- setup kernels ----------------
__global__ void k_count(const int* __restrict__ eidx, const int* __restrict__ etyp,
                        int E, int N) {
    int e = blockIdx.x * blockDim.x + threadIdx.x;
    if (e >= E) return;
    int dst = eidx[E + e];
    int rel = etyp[e];
    atomicAdd(&g_cnt[rel * N + dst], 1);
    atomicAdd(&g_hist[dst], 1);
}

// single-pass exclusive scan of g_hist -> g_cursor, decoupled chain.
// 98 blocks of 1024 (all resident on 148 SMs -> chained spin is safe).
__global__ void k_scan(int N) {
    __shared__ int sh[1024];
    __shared__ int s_prev;
    int t = threadIdx.x, blk = blockIdx.x;
    int i = blk * 1024 + t;
    int x = (i < N) ? g_hist[i] : 0;
    sh[t] = x;
    __syncthreads();
    for (int off = 1; off < 1024; off <<= 1) {
        int v = (t >= off) ? sh[t - off] : 0;
        __syncthreads();
        sh[t] += v;
        __syncthreads();
    }
    if (t == 0) {
        int prev = 0;
        if (blk > 0) {
            int v;
            do {
                v = atomicAdd(&g_chain[blk - 1], 0);
                if (v == 0) __nanosleep(60);
            } while (v == 0);
            prev = v - 1;
        }
        atomicExch(&g_chain[blk], prev + sh[1023] + 1);
        s_prev = prev;
    }
    __syncthreads();
    if (i < N) g_cursor[i] = s_prev + sh[t] - x;
}

__global__ void k_scatter(const int* __restrict__ eidx, const int* __restrict__ etyp,
                          int E, int N) {
    int e = blockIdx.x * blockDim.x + threadIdx.x;
    if (e >= E) return;
    int src = eidx[e];
    int dst = eidx[E + e];
    int rel = etyp[e];
    int p = atomicAdd(&g_cursor[dst], 1);
    int c = g_cnt[rel * N + dst];
    float sc = 1.0f / (float)(c > 1 ? c : 1);
    g_edge[p] = make_int4(src, dst, rel, __float_as_int(sc));
}

// restore invariants for the next call
__global__ void k_cleanup(int N, int RN, int E, int Epad) {
    int i = blockIdx.x * blockDim.x + threadIdx.x;
    if (i < RN)  g_cnt[i] = 0;
    if (i < N)   g_hist[i] = 0;
    if (i < 256) g_chain[i] = 0;
    if (i < Epad - E) g_edge[E + i] = make_int4(0, 0, 0, 0);
}

// ---------------- final dense pass: out = (relu?)(x @ root + bias + agg) ----------------
// Also zeroes the agg cells it consumed (restores invariant for next k_edge).
#define GROWS 80
#define GTHREADS 256
__global__ __launch_bounds__(GTHREADS)
void k_final(const float* __restrict__ x, const float* __restrict__ root,
             const float* __restrict__ bias, float* __restrict__ agg,
             float* __restrict__ out, int N, int relu_out) {
    extern __shared__ float sm_i[];
    float* xs = sm_i;                 // 80 * 101
    float* rs = sm_i + GROWS * 101;   // 100 * 100
    int t = threadIdx.x;
    int rowbase = blockIdx.x * GROWS;

    for (int i = t; i < HID * HID; i += GTHREADS) rs[i] = root[i];
    for (int i = t; i < GROWS * HID; i += GTHREADS) {
        int rr = i / HID, c = i - rr * HID;
        int row = rowbase + rr;
        xs[rr * 101 + c] = (row < N) ? x[row * HID + c] : 0.0f;
    }
    __syncthreads();
    if (t >= 250) return;

    int q = t % 25;
    int rg = t / 25;
    float4 b4 = *reinterpret_cast<const float4*>(bias + 4 * q);
    float acc[8][4];
#pragma unroll
    for (int i = 0; i < 8; i++) {
        acc[i][0] = b4.x; acc[i][1] = b4.y; acc[i][2] = b4.z; acc[i][3] = b4.w;
    }
#pragma unroll 4
    for (int k = 0; k < HID; k++) {
        float4 r4 = *reinterpret_cast<const float4*>(rs + k * HID + 4 * q);
#pragma unroll
        for (int i = 0; i < 8; i++) {
            float xv = xs[(rg * 8 + i) * 101 + k];
            acc[i][0] = fmaf(xv, r4.x, acc[i][0]);
            acc[i][1] = fmaf(xv, r4.y, acc[i][1]);
            acc[i][2] = fmaf(xv, r4.z, acc[i][2]);
            acc[i][3] = fmaf(xv, r4.w, acc[i][3]);
        }
    }
#pragma unroll
    for (int i = 0; i < 8; i++) {
        int row = rowbase + rg * 8 + i;
        if (row < N) {
            float4* ap = reinterpret_cast<float4*>(agg + (size_t)row * HID + 4 * q);
            float4 a = *ap;
            *ap = make_float4(0.0f, 0.0f, 0.0f, 0.0f);   // restore invariant
            float4 o;
            o.x = acc[i][0] + a.x; o.y = acc[i][1] + a.y;
            o.z = acc[i][2] + a.z; o.w = acc[i][3] + a.w;
            if (relu_out) {
                o.x = fmaxf(o.x, 0.0f); o.y = fmaxf(o.y, 0.0f);
                o.z = fmaxf(o.z, 0.0f); o.w = fmaxf(o.w, 0.0f);
            }
            *reinterpret_cast<float4*>(out + (size_t)row * HID + 4 * q) = o;
        }
    }
}

// ---------------- edge kernel (R11 core) ----------------
// Per tile of 96 dst-sorted edges: in-tile rel counting sort (warps 0-2) +
// dst-segment list (warps 3-5); x rows cp.async-staged in SORTED order
// (stride 100, rows 16B-aligned); phase2: thread (b,e) transforms sorted
// row e in place; phase3: 2 warps per dst-segment (column split) sum rows
// via fwd[] and emit red.add.v4.f32 into g_agg.
__device__ __forceinline__ void sort_tile96(const int4* md, int* sinv, int* fwd,
                                            int* srl, float* ssc, int* segs,
                                            int* scnt, int* sbase, int* swx,
                                            int t, int lane, int wrp) {
    int myrel = 0, myrank = 0;
    if (t < ETILE) {
        myrel = md[t].z;
        unsigned m = __match_any_sync(0xFFFFFFFFu, myrel);
        myrank = __popc(m & ((1u << lane) - 1u));
        if ((int)(__ffs(m) - 1) == lane) scnt[wrp * 16 + myrel] = __popc(m);
    } else if (t < 2 * ETILE) {
        int p = t - ETILE;
        bool head = (p == 0) || (md[p - 1].y != md[p].y);
        unsigned bal = __ballot_sync(0xFFFFFFFFu, head);
        if (lane == 0) swx[wrp - 3] = __popc(bal);
    }
    __syncthreads();
    if (t < 16) {
        int c0 = scnt[t], c1 = scnt[16 + t], c2 = scnt[32 + t];
        int tot = c0 + c1 + c2;
        int run = tot;
#pragma unroll
        for (int d = 1; d < 16; d <<= 1) {
            int v = __shfl_up_sync(0xFFFFu, run, d);
            if (lane >= d) run += v;
        }
        int off = run - tot;
        sbase[t]      = off;
        sbase[16 + t] = off + c0;
        sbase[32 + t] = off + c0 + c1;
    }
    if (t == 2 * ETILE) {
        int a = swx[0], b2 = swx[1], c = swx[2];
        int ns = a + b2 + c;
        swx[3] = 0; swx[4] = a; swx[5] = a + b2; swx[6] = ns;
        segs[ns] = ETILE;   // sentinel
    }
    __syncthreads();
    if (t < ETILE) {
        int pos = sbase[wrp * 16 + myrel] + myrank;
        sinv[pos] = t;
        fwd[t] = pos;
        srl[pos] = myrel;
        ssc[pos] = __int_as_float(md[t].w);
    } else if (t < 2 * ETILE) {
        int p = t - ETILE;
        bool head = (p == 0) || (md[p - 1].y != md[p].y);
        unsigned bal = __ballot_sync(0xFFFFFFFFu, head);
        if (head) segs[swx[3 + (wrp - 3)] + __popc(bal & ((1u << lane) - 1u))] = p;
    } else if (t < 2 * ETILE + 48) {
        scnt[t - 2 * ETILE] = 0;   // re-zero for next sort
    }
    __syncthreads();
}

// stage x rows of a tile into xs in SORTED order (row j holds edge sinv[j]).
__device__ __forceinline__ void stage_x(const float* __restrict__ x, const int4* md,
                                        const int* sinv, float* xs, int t) {
#pragma unroll
    for (int k = 0; k < (ETILE * 25) / ETHREADS; k++) {   // 5
        int idx = t + k * ETHREADS;
        int j = idx / 25, c4 = idx - j * 25;
        int src = md[sinv[j]].x;
        cpa16(smaddr(xs + j * 100 + c4 * 4), x + (size_t)src * HID + c4 * 4);
    }
}

__global__ __launch_bounds__(ETHREADS)
void k_edge(const float* __restrict__ x, const float* __restrict__ w,
            float* __restrict__ agg, int ntiles) {
    extern __shared__ float sm_e[];
    float* ws    = sm_e;                               // 16*2004 floats
    float* xs0   = ws + NREL * WSTRIDE;                // 96*100
    float* xs1   = xs0 + ETILE * 100;                  // 96*100
    int4*  mds0  = (int4*)(xs1 + ETILE * 100);         // 3 * 96 int4
    int*   sinv0 = (int*)(mds0 + 3 * ETILE);
    int*   sinv1 = sinv0 + ETILE;
    int*   fwd0  = sinv1 + ETILE;
    int*   fwd1  = fwd0 + ETILE;
    int*   srl0  = fwd1 + ETILE;
    int*   srl1  = srl0 + ETILE;
    float* ssc0  = (float*)(srl1 + ETILE);
    float* ssc1  = ssc0 + ETILE;
    int*   segs0 = (int*)(ssc1 + ETILE);               // 97
    int*   segs1 = segs0 + ETILE + 1;                  // 97
    int*   scnt  = segs1 + ETILE + 1;                  // 48
    int*   sbase = scnt + 48;                          // 48
    int*   swx   = sbase + 48;                         // 8

    int t = threadIdx.x;
    int lane = t & 31;
    int wrp = t >> 5;
    int b = t / ETILE;          // 0..4, warp-uniform (96 = 3 warps)
    int e = t - b * ETILE;      // 0..95

    for (int i = t; i < NREL * 2000; i += ETHREADS) {
        int r = i / 2000;
        ws[r * WSTRIDE + (i - r * 2000)] = w[i];
    }
    if (t < 48) scnt[t] = 0;

    int grid = gridDim.x;
    int tile0 = blockIdx.x;

    // ---- preloop: meta(t0) -> sort -> stage x(t0); prefetch meta(t0+g) ----
    if (t < ETILE) cpa16(smaddr(mds0 + t), &g_edge[(size_t)tile0 * ETILE + t]);
    CPA_COMMIT();
    CPA_WAIT0();
    __syncthreads();
    sort_tile96(mds0, sinv0, fwd0, srl0, ssc0, segs0, scnt, sbase, swx, t, lane, wrp);
    stage_x(x, mds0, sinv0, xs0, t);
    CPA_COMMIT();
    if (tile0 + grid < ntiles && t < ETILE)
        cpa16(smaddr(mds0 + ETILE + t), &g_edge[(size_t)(tile0 + grid) * ETILE + t]);
    CPA_COMMIT();

    int par = 0, rot = 0;
    for (int tile = tile0; tile < ntiles; tile += grid) {
        CPA_WAIT0();                  // x(tile) staged; meta(tile+g) arrived
        __syncthreads();
        int nseg_cur = swx[6];        // nseg of current tile
        int nxt = tile + grid;

        float* xs_c  = par ? xs1 : xs0;
        float* xs_n  = par ? xs0 : xs1;
        int*   sinv_n = par ? sinv0 : sinv1;
        int*   fwd_c = par ? fwd1 : fwd0;
        int*   fwd_n = par ? fwd0 : fwd1;
        int*   srl_c = par ? srl1 : srl0;
        int*   srl_n = par ? srl0 : srl1;
        float* ssc_c = par ? ssc1 : ssc0;
        float* ssc_n = par ? ssc0 : ssc1;
        int*   segs_c = par ? segs1 : segs0;
        int*   segs_n = par ? segs0 : segs1;
        const int4* mdc = mds0 + rot * ETILE;

        // ---- sort + stage tile (nxt); prefetch meta(nxt+g) ----
        if (nxt < ntiles) {
            const int4* mdn = mds0 + ((rot + 1) % 3) * ETILE;
            sort_tile96(mdn, sinv_n, fwd_n, srl_n, ssc_n, segs_n,
                        scnt, sbase, swx, t, lane, wrp);
            stage_x(x, mdn, sinv_n, xs_n, t);
        }
        CPA_COMMIT();
        if (nxt + grid < ntiles && t < ETILE)
            cpa16(smaddr(mds0 + ((rot + 2) % 3) * ETILE + t),
                  &g_edge[(size_t)(nxt + grid) * ETILE + t]);
        CPA_COMMIT();

        // ---- phase 2: transform sorted row e (block b), write in place ----
        {
            int rel  = srl_c[e];
            float sc = ssc_c[e];
            float* xp = xs_c + e * 100 + b * CB;
            float xv[CB];
            const float4* xp4 = reinterpret_cast<const float4*>(xp);
#pragma unroll
            for (int k = 0; k < 5; k++) {
                float4 v = xp4[k];
                xv[4 * k + 0] = v.x; xv[4 * k + 1] = v.y;
                xv[4 * k + 2] = v.z; xv[4 * k + 3] = v.w;
            }
            const float* wb = ws + rel * WSTRIDE + b * (CB * CB);
            float acc[CB];
#pragma unroll
            for (int d = 0; d < CB; d++) acc[d] = 0.0f;
#pragma unroll
            for (int c = 0; c < CB; c++) {
                float xvc = xv[c];
                const float4* w4 = reinterpret_cast<const float4*>(wb + c * CB);
#pragma unroll
                for (int d4 = 0; d4 < 5; d4++) {
                    float4 wv = w4[d4];
                    acc[4 * d4 + 0] = fmaf(xvc, wv.x, acc[4 * d4 + 0]);
                    acc[4 * d4 + 1] = fmaf(xvc, wv.y, acc[4 * d4 + 1]);
                    acc[4 * d4 + 2] = fmaf(xvc, wv.z, acc[4 * d4 + 2]);
                    acc[4 * d4 + 3] = fmaf(xvc, wv.w, acc[4 * d4 + 3]);
                }
            }
            float4* wp = reinterpret_cast<float4*>(xp);
#pragma unroll
            for (int d4 = 0; d4 < 5; d4++) {
                float4 v;
                v.x = acc[4 * d4 + 0] * sc; v.y = acc[4 * d4 + 1] * sc;
                v.z = acc[4 * d4 + 2] * sc; v.w = acc[4 * d4 + 3] * sc;
                wp[d4] = v;
            }
        }
        __syncthreads();              // res (in xs_c) complete

        // ---- phase 3: 2 warps per dst-segment (column split) + v4 RED ----
        for (int ss = wrp; ss < 2 * nseg_cur; ss += ETHREADS / 32) {
            int s = ss >> 1, half = ss & 1;
            int a0 = segs_c[s], a1 = segs_c[s + 1];
            int cbase = half ? 13 : 0;
            int ccnt  = half ? 12 : 13;
            if (lane < ccnt) {
                int c4 = cbase + lane;
                float4 a4 = make_float4(0.0f, 0.0f, 0.0f, 0.0f);
                for (int ee = a0; ee < a1; ee++) {
                    int rr = fwd_c[ee];
                    float4 v = *reinterpret_cast<const float4*>(
                        xs_c + rr * 100 + 4 * c4);
                    a4.x += v.x; a4.y += v.y; a4.z += v.z; a4.w += v.w;
                }
                red_add_v4(agg + (size_t)mdc[a0].y * HID + 4 * c4, a4);
            }
        }
        __syncthreads();              // mdc/xs_c readers done before reuse
        rot = (rot + 1) % 3;
        par ^= 1;
    }
}

// ---------------- host launcher ----------------
extern "C" void kernel_launch(void* const* d_in, const int* in_sizes, int n_in,
                              void* d_out, int out_size) {
    const float* node_emb = (const float*)d_in[0];
    const float* w1    = (const float*)d_in[1];
    const float* root1 = (const float*)d_in[2];
    const float* bias1 = (const float*)d_in[3];
    const float* w2    = (const float*)d_in[4];
    const float* root2 = (const float*)d_in[5];
    const float* bias2 = (const float*)d_in[6];
    const int*   eidx  = (const int*)d_in[7];
    const int*   etyp  = (const int*)d_in[8];
    float* out = (float*)d_out;

    int N = in_sizes[0] / HID;
    int E = in_sizes[8];
    if (N > MAXN) N = MAXN;
    int ntiles = (E + ETILE - 1) / ETILE;
    int Epad = ntiles * ETILE;
    if (Epad > MAXE) { Epad = MAXE; ntiles = Epad / ETILE; }

    float *h1 = nullptr, *agg = nullptr;
    cudaGetSymbolAddress((void**)&h1, g_h1);
    cudaGetSymbolAddress((void**)&agg, g_agg);

    const int EDGE_SMEM = (NREL * WSTRIDE + 2 * ETILE * 100) * 4   // ws + xs0/xs1
                        + 3 * ETILE * 16                            // meta x3
                        + (6 * ETILE + 2 * ETILE
                           + 2 * (ETILE + 1) + 48 + 48 + 8) * 4;
    const int INIT_SMEM = (GROWS * 101 + HID * HID) * 4;
    cudaFuncSetAttribute(k_edge, cudaFuncAttributeMaxDynamicSharedMemorySize, EDGE_SMEM);
    cudaFuncSetAttribute(k_final, cudaFuncAttributeMaxDynamicSharedMemorySize, INIT_SMEM);

    int RN = NREL * N;
    int nb = (N + 1023) / 1024;      // 98 blocks, all resident
    int init_grid = (N + GROWS - 1) / GROWS;
    const int EDGE_GRID = 148;

    // preprocessing (g_cnt/g_hist/g_chain zero at entry by invariant)
    k_count<<<(E + 255) / 256, 256>>>(eidx, etyp, E, N);          // launch 1
    k_scan<<<nb, 1024>>>(N);                                       // launch 2
    k_scatter<<<(E + 255) / 256, 256>>>(eidx, etyp, E, N);         // launch 3

    // layer 1 edge aggregation into g_agg (zero at entry)        // launch 4 (profiled)
    k_edge<<<EDGE_GRID, ETHREADS, EDGE_SMEM>>>(node_emb, w1, agg, ntiles);
    // h1 = relu(emb @ root1 + bias1 + agg); agg zeroed           // launch 5
    k_final<<<init_grid, GTHREADS, INIT_SMEM>>>(node_emb, root1, bias1, agg, h1, N, 1);

    // layer 2 (h1 already post-relu)                              // launch 6
    k_edge<<<EDGE_GRID, ETHREADS, EDGE_SMEM>>>(h1, w2, agg, ntiles);
    // out = h1 @ root2 + bias2 + agg; agg zeroed                  // launch 7
    k_final<<<init_grid, GTHREADS, INIT_SMEM>>>(h1, root2, bias2, agg, out, N, 0);

    // restore invariants for next call                            // launch 8
    k_cleanup<<<(RN + 255) / 256, 256>>>(N, RN, E, Epad);
}

// round 14
// speedup vs baseline: 1.3807x; 1.3807x over previous
#include <cuda_runtime.h>
#include <cstdint>

#define HID      100
#define NREL     16
#define NBLK     5
#define CB       20
#define MAXN     100000
#define MAXRN    (NREL * MAXN)
#define MAXE     1600128      // >= ntiles*ETILE for E=1.6M
#define WSTRIDE  2004         // per-relation weight stride (2000 used + 4 pad)
#define ETILE    96
#define ETHREADS 480
#define XROWS    97           // 96 data rows + scratch row 96 for dummy outputs

// ---------------- scratch (device globals; no allocations allowed) ----------------
// Invariant at entry (static zero-init + k_cleanup): g_cnt/g_hist/g_chain zero,
// g_edge[E..Epad) inert.
__device__ int   g_cnt[MAXRN];
__device__ int   g_hist[MAXN];
__device__ int   g_cursor[MAXN];
__device__ int   g_chain[256];
__device__ int4  g_edge[MAXE];      // dst-sorted: {src, dst, rel, scale-bits}
__device__ float g_h1[MAXN * HID];  // layer-1 output (pre-relu)

// ---------------- helpers ----------------
__device__ __forceinline__ uint32_t smaddr(const void* p) {
    return (uint32_t)__cvta_generic_to_shared(p);
}
__device__ __forceinline__ void cpa16(uint32_t s, const void* g) {
    asm volatile("cp.async.cg.shared.global [%0], [%1], 16;" :: "r"(s), "l"(g));
}
#define CPA_COMMIT() asm volatile("cp.async.commit_group;" ::: "memory")
#define CPA_WAIT0()  asm volatile("cp.async.wait_group 0;" ::: "memory")

__device__ __forceinline__ void red_add_v4(float* gptr, float4 v) {
    asm volatile("red.global.add.v4.f32 [%0], {%1, %2, %3, %4};"
                 :: "l"(gptr), "f"(v.x), "f"(v.y), "f"(v.z), "f"(v.w) : "memory");
}

// ---------------- dense init body: out = (relu?x) @ root + bias ----------------
#define GROWS 80
#define GTHREADS 256
__device__ __forceinline__ void init_body(const float* __restrict__ x,
                                          const float* __restrict__ root,
                                          const float* __restrict__ bias,
                                          float* __restrict__ out,
                                          int N, int do_relu, int rowbase,
                                          float* sm) {
    float* xs = sm;                   // 80 * 101
    float* rs = sm + GROWS * 101;     // 100 * 100
    int t = threadIdx.x;

    for (int i = t; i < HID * HID; i += GTHREADS) rs[i] = root[i];
    for (int i = t; i < GROWS * HID; i += GTHREADS) {
        int rr = i / HID, c = i - rr * HID;
        int row = rowbase + rr;
        float v = (row < N) ? x[(size_t)row * HID + c] : 0.0f;
        if (do_relu) v = fmaxf(v, 0.0f);
        xs[rr * 101 + c] = v;
    }
    __syncthreads();
    if (t >= 250) return;

    int q = t % 25;
    int rg = t / 25;
    float4 b4 = *reinterpret_cast<const float4*>(bias + 4 * q);
    float acc[8][4];
#pragma unroll
    for (int i = 0; i < 8; i++) {
        acc[i][0] = b4.x; acc[i][1] = b4.y; acc[i][2] = b4.z; acc[i][3] = b4.w;
    }
#pragma unroll 4
    for (int k = 0; k < HID; k++) {
        float4 r4 = *reinterpret_cast<const float4*>(rs + k * HID + 4 * q);
#pragma unroll
        for (int i = 0; i < 8; i++) {
            float xv = xs[(rg * 8 + i) * 101 + k];
            acc[i][0] = fmaf(xv, r4.x, acc[i][0]);
            acc[i][1] = fmaf(xv, r4.y, acc[i][1]);
            acc[i][2] = fmaf(xv, r4.z, acc[i][2]);
            acc[i][3] = fmaf(xv, r4.w, acc[i][3]);
        }
    }
#pragma unroll
    for (int i = 0; i < 8; i++) {
        int row = rowbase + rg * 8 + i;
        if (row < N) {
            float4 o;
            o.x = acc[i][0]; o.y = acc[i][1]; o.z = acc[i][2]; o.w = acc[i][3];
            *reinterpret_cast<float4*>(out + (size_t)row * HID + 4 * q) = o;
        }
    }
}

// ---------------- launch 0: fused edge-count + layer-1 init ----------------
__global__ __launch_bounds__(GTHREADS)
void k_pre(const int* __restrict__ eidx, const int* __restrict__ etyp, int E, int N,
           const float* __restrict__ emb, const float* __restrict__ root1,
           const float* __restrict__ bias1, float* __restrict__ h1, int cntBlocks) {
    extern __shared__ float sm_i[];
    if ((int)blockIdx.x < cntBlocks) {
        int e = blockIdx.x * GTHREADS + threadIdx.x;
        if (e < E) {
            int dst = eidx[E + e];
            int rel = etyp[e];
            atomicAdd(&g_cnt[rel * N + dst], 1);
            atomicAdd(&g_hist[dst], 1);
        }
    } else {
        int bid = blockIdx.x - cntBlocks;
        init_body(emb, root1, bias1, h1, N, 0, bid * GROWS, sm_i);
    }
}

// ---------------- launch 4: layer-2 init ----------------
__global__ __launch_bounds__(GTHREADS)
void k_init(const float* __restrict__ x, const float* __restrict__ root,
            const float* __restrict__ bias, float* __restrict__ out,
            int N, int do_relu) {
    extern __shared__ float sm_i[];
    init_body(x, root, bias, out, N, do_relu, blockIdx.x * GROWS, sm_i);
}

// single-pass exclusive scan of g_hist -> g_cursor, decoupled chain.
__global__ void k_scan(int N) {
    __shared__ int sh[1024];
    __shared__ int s_prev;
    int t = threadIdx.x, blk = blockIdx.x;
    int i = blk * 1024 + t;
    int x = (i < N) ? g_hist[i] : 0;
    sh[t] = x;
    __syncthreads();
    for (int off = 1; off < 1024; off <<= 1) {
        int v = (t >= off) ? sh[t - off] : 0;
        __syncthreads();
        sh[t] += v;
        __syncthreads();
    }
    if (t == 0) {
        int prev = 0;
        if (blk > 0) {
            int v;
            do {
                v = atomicAdd(&g_chain[blk - 1], 0);
                if (v == 0) __nanosleep(60);
            } while (v == 0);
            prev = v - 1;
        }
        atomicExch(&g_chain[blk], prev + sh[1023] + 1);
        s_prev = prev;
    }
    __syncthreads();
    if (i < N) g_cursor[i] = s_prev + sh[t] - x;
}

__global__ void k_scatter(const int* __restrict__ eidx, const int* __restrict__ etyp,
                          int E, int N) {
    int e = blockIdx.x * blockDim.x + threadIdx.x;
    if (e >= E) return;
    int src = eidx[e];
    int dst = eidx[E + e];
    int rel = etyp[e];
    int p = atomicAdd(&g_cursor[dst], 1);
    int c = g_cnt[rel * N + dst];
    float sc = 1.0f / (float)(c > 1 ? c : 1);
    g_edge[p] = make_int4(src, dst, rel, __float_as_int(sc));
}

__global__ void k_cleanup(int N, int RN, int E, int Epad) {
    int i = blockIdx.x * blockDim.x + threadIdx.x;
    if (i < RN)  g_cnt[i] = 0;
    if (i < N)   g_hist[i] = 0;
    if (i < 256) g_chain[i] = 0;
    if (i < Epad - E) g_edge[E + i] = make_int4(0, 0, 0, 0);
}

// ---------------- edge kernel ----------------
// Per tile of 96 dst-sorted edges:
//  in-tile rel counting sort (warps 0-2) + dst segments (warps 3-5) + padded
//  PAIR list (16 head lanes): each pair = two rel-identical sorted rows (odd
//  groups padded with a scale-0 dummy whose output goes to scratch row 96).
//  x rows cp.async-staged in sorted order (stride 100).
//  phase2: thread (b, p) transforms BOTH rows of pair p for block b with ONE
//  weight pass (halves weight LDS.128 return traffic - the measured bottleneck).
//  phase3: 2 warps per dst-segment (column split) sum rows via fwd[] and emit
//  red.add.v4 into out.
__device__ __forceinline__ void sort_tile96(const int4* md, int* sinv, int* fwd,
                                            int* srl, float* ssc, int* segs, int* pp,
                                            int* scnt, int* sbase, int* swx,
                                            int t, int lane, int wrp) {
    int myrel = 0, myrank = 0;
    if (t < ETILE) {
        myrel = md[t].z;
        unsigned m = __match_any_sync(0xFFFFFFFFu, myrel);
        myrank = __popc(m & ((1u << lane) - 1u));
        if ((int)(__ffs(m) - 1) == lane) scnt[wrp * 16 + myrel] = __popc(m);
    } else if (t < 2 * ETILE) {
        int p = t - ETILE;
        bool head = (p == 0) || (md[p - 1].y != md[p].y);
        unsigned bal = __ballot_sync(0xFFFFFFFFu, head);
        if (lane == 0) swx[wrp - 3] = __popc(bal);
    }
    __syncthreads();
    if (t < 16) {
        int c0 = scnt[t], c1 = scnt[16 + t], c2 = scnt[32 + t];
        int tot = c0 + c1 + c2;
        int run = tot;
#pragma unroll
        for (int d = 1; d < 16; d <<= 1) {
            int v = __shfl_up_sync(0xFFFFu, run, d);
            if (lane >= d) run += v;
        }
        int off = run - tot;
        sbase[t]      = off;
        sbase[16 + t] = off + c0;
        sbase[32 + t] = off + c0 + c1;
        // padded pair list for this rel group
        int pcnt = (tot + 1) >> 1;
        int runp = pcnt;
#pragma unroll
        for (int d = 1; d < 16; d <<= 1) {
            int v = __shfl_up_sync(0xFFFFu, runp, d);
            if (lane >= d) runp += v;
        }
        int poff = runp - pcnt;
        for (int j = 0; j < pcnt; j++)
            pp[poff + j] = (off + 2 * j) | ((2 * j + 1 < tot) ? 0x10000 : 0);
        if (t == 15) swx[7] = runp;   // npairs
    }
    if (t == 2 * ETILE) {
        int a = swx[0], b2 = swx[1], c = swx[2];
        int ns = a + b2 + c;
        swx[3] = 0; swx[4] = a; swx[5] = a + b2; swx[6] = ns;
        segs[ns] = ETILE;   // sentinel
    }
    __syncthreads();
    if (t < ETILE) {
        int pos = sbase[wrp * 16 + myrel] + myrank;
        sinv[pos] = t;
        fwd[t] = pos;
        srl[pos] = myrel;
        ssc[pos] = __int_as_float(md[t].w);
    } else if (t < 2 * ETILE) {
        int p = t - ETILE;
        bool head = (p == 0) || (md[p - 1].y != md[p].y);
        unsigned bal = __ballot_sync(0xFFFFFFFFu, head);
        if (head) segs[swx[3 + (wrp - 3)] + __popc(bal & ((1u << lane) - 1u))] = p;
    } else if (t < 2 * ETILE + 48) {
        scnt[t - 2 * ETILE] = 0;   // re-zero for next sort
    }
    __syncthreads();
}

__device__ __forceinline__ void stage_x(const float* __restrict__ x, const int4* md,
                                        const int* sinv, float* xs, int t) {
#pragma unroll
    for (int k = 0; k < (ETILE * 25) / ETHREADS; k++) {   // 5
        int idx = t + k * ETHREADS;
        int j = idx / 25, c4 = idx - j * 25;
        int src = md[sinv[j]].x;
        cpa16(smaddr(xs + j * 100 + c4 * 4), x + (size_t)src * HID + c4 * 4);
    }
}

__global__ __launch_bounds__(ETHREADS)
void k_edge(const float* __restrict__ x, const float* __restrict__ w,
            float* __restrict__ out, int ntiles, int do_relu) {
    extern __shared__ float sm_e[];
    float* ws    = sm_e;                               // 16*2004 floats
    float* xs0   = ws + NREL * WSTRIDE;                // 97*100
    float* xs1   = xs0 + XROWS * 100;                  // 97*100
    int4*  mds0  = (int4*)(xs1 + XROWS * 100);         // 3*96 int4 (16B aligned)
    int*   sinv0 = (int*)(mds0 + 3 * ETILE);
    int*   sinv1 = sinv0 + ETILE;
    int*   fwd0  = sinv1 + ETILE;
    int*   fwd1  = fwd0 + ETILE;
    int*   srl0  = fwd1 + ETILE;
    int*   srl1  = srl0 + ETILE;
    float* ssc0  = (float*)(srl1 + ETILE);
    float* ssc1  = ssc0 + ETILE;
    int*   segs0 = (int*)(ssc1 + ETILE);               // 97
    int*   segs1 = segs0 + ETILE + 1;                  // 97
    int*   pp0   = segs1 + ETILE + 1;                  // 64
    int*   pp1   = pp0 + 64;                           // 64
    int*   scnt  = pp1 + 64;                           // 48
    int*   sbase = scnt + 48;                          // 48
    int*   swx   = sbase + 48;                         // 16

    int t = threadIdx.x;
    int lane = t & 31;
    int wrp = t >> 5;

    for (int i = t; i < NREL * 2000; i += ETHREADS) {
        int r = i / 2000;
        ws[r * WSTRIDE + (i - r * 2000)] = w[i];
    }
    if (t < 48) scnt[t] = 0;

    int grid = gridDim.x;
    int tile0 = blockIdx.x;

    // ---- preloop ----
    if (t < ETILE) cpa16(smaddr(mds0 + t), &g_edge[(size_t)tile0 * ETILE + t]);
    CPA_COMMIT();
    CPA_WAIT0();
    __syncthreads();
    sort_tile96(mds0, sinv0, fwd0, srl0, ssc0, segs0, pp0, scnt, sbase, swx, t, lane, wrp);
    stage_x(x, mds0, sinv0, xs0, t);
    CPA_COMMIT();
    if (tile0 + grid < ntiles && t < ETILE)
        cpa16(smaddr(mds0 + ETILE + t), &g_edge[(size_t)(tile0 + grid) * ETILE + t]);
    CPA_COMMIT();

    int par = 0, rot = 0;
    for (int tile = tile0; tile < ntiles; tile += grid) {
        CPA_WAIT0();                  // x(tile) staged; meta(tile+g) arrived
        __syncthreads();
        int nseg_cur   = swx[6];      // snapshots before next sort overwrites
        int npairs_cur = swx[7];
        int nxt = tile + grid;

        float* xs_c  = par ? xs1 : xs0;
        float* xs_n  = par ? xs0 : xs1;
        int*   sinv_n = par ? sinv0 : sinv1;
        int*   fwd_c = par ? fwd1 : fwd0;
        int*   fwd_n = par ? fwd0 : fwd1;
        int*   srl_c = par ? srl1 : srl0;
        int*   srl_n = par ? srl0 : srl1;
        float* ssc_c = par ? ssc1 : ssc0;
        float* ssc_n = par ? ssc0 : ssc1;
        int*   segs_c = par ? segs1 : segs0;
        int*   segs_n = par ? segs0 : segs1;
        int*   pp_c  = par ? pp1 : pp0;
        int*   pp_n  = par ? pp0 : pp1;
        const int4* mdc = mds0 + rot * ETILE;

        // ---- sort + stage tile (nxt); prefetch meta(nxt+g) ----
        if (nxt < ntiles) {
            const int4* mdn = mds0 + ((rot + 1) % 3) * ETILE;
            sort_tile96(mdn, sinv_n, fwd_n, srl_n, ssc_n, segs_n, pp_n,
                        scnt, sbase, swx, t, lane, wrp);
            stage_x(x, mdn, sinv_n, xs_n, t);
        }
        CPA_COMMIT();
        if (nxt + grid < ntiles && t < ETILE)
            cpa16(smaddr(mds0 + ((rot + 2) % 3) * ETILE + t),
                  &g_edge[(size_t)(nxt + grid) * ETILE + t]);
        CPA_COMMIT();

        // ---- phase 2: pair transform (block b, pair p), in place ----
        if (t < 320) {
            int p = t & 63;
            if (p < npairs_cur) {
                int b = t >> 6;                    // 0..4
                int v = pp_c[p];
                int r0 = v & 0xffff;
                int val1 = v >> 16;                // 1 if second row real
                int rr1 = r0 + val1;               // read row (r0 if dummy)
                int wr1 = val1 ? (r0 + 1) : 96;    // write row (scratch if dummy)
                int rel = srl_c[r0];
                float sc0 = ssc_c[r0];
                float sc1 = val1 ? ssc_c[r0 + 1] : 0.0f;

                float xv0[CB], xv1[CB];
                const float4* x0 = reinterpret_cast<const float4*>(xs_c + r0 * 100 + b * CB);
                const float4* x1 = reinterpret_cast<const float4*>(xs_c + rr1 * 100 + b * CB);
#pragma unroll
                for (int k = 0; k < 5; k++) {
                    float4 a = x0[k], bb = x1[k];
                    if (do_relu) {
                        a.x = fmaxf(a.x, 0.0f); a.y = fmaxf(a.y, 0.0f);
                        a.z = fmaxf(a.z, 0.0f); a.w = fmaxf(a.w, 0.0f);
                        bb.x = fmaxf(bb.x, 0.0f); bb.y = fmaxf(bb.y, 0.0f);
                        bb.z = fmaxf(bb.z, 0.0f); bb.w = fmaxf(bb.w, 0.0f);
                    }
                    xv0[4 * k] = a.x; xv0[4 * k + 1] = a.y; xv0[4 * k + 2] = a.z; xv0[4 * k + 3] = a.w;
                    xv1[4 * k] = bb.x; xv1[4 * k + 1] = bb.y; xv1[4 * k + 2] = bb.z; xv1[4 * k + 3] = bb.w;
                }

                const float* wb = ws + rel * WSTRIDE + b * (CB * CB);
                float a0[CB], a1[CB];
#pragma unroll
                for (int d = 0; d < CB; d++) { a0[d] = 0.0f; a1[d] = 0.0f; }
#pragma unroll
                for (int c = 0; c < CB; c++) {
                    float c0 = xv0[c], c1 = xv1[c];
                    const float4* w4 = reinterpret_cast<const float4*>(wb + c * CB);
#pragma unroll
                    for (int d4 = 0; d4 < 5; d4++) {
                        float4 wv = w4[d4];
                        a0[4 * d4]     = fmaf(c0, wv.x, a0[4 * d4]);
                        a0[4 * d4 + 1] = fmaf(c0, wv.y, a0[4 * d4 + 1]);
                        a0[4 * d4 + 2] = fmaf(c0, wv.z, a0[4 * d4 + 2]);
                        a0[4 * d4 + 3] = fmaf(c0, wv.w, a0[4 * d4 + 3]);
                        a1[4 * d4]     = fmaf(c1, wv.x, a1[4 * d4]);
                        a1[4 * d4 + 1] = fmaf(c1, wv.y, a1[4 * d4 + 1]);
                        a1[4 * d4 + 2] = fmaf(c1, wv.z, a1[4 * d4 + 2]);
                        a1[4 * d4 + 3] = fmaf(c1, wv.w, a1[4 * d4 + 3]);
                    }
                }
                float4* w0 = reinterpret_cast<float4*>(xs_c + r0 * 100 + b * CB);
                float4* w1p = reinterpret_cast<float4*>(xs_c + wr1 * 100 + b * CB);
#pragma unroll
                for (int d4 = 0; d4 < 5; d4++) {
                    float4 o0, o1;
                    o0.x = a0[4 * d4] * sc0;     o0.y = a0[4 * d4 + 1] * sc0;
                    o0.z = a0[4 * d4 + 2] * sc0; o0.w = a0[4 * d4 + 3] * sc0;
                    o1.x = a1[4 * d4] * sc1;     o1.y = a1[4 * d4 + 1] * sc1;
                    o1.z = a1[4 * d4 + 2] * sc1; o1.w = a1[4 * d4 + 3] * sc1;
                    w0[d4] = o0;
                    w1p[d4] = o1;
                }
            }
        }
        __syncthreads();              // transformed rows complete

        // ---- phase 3: 2 warps per dst-segment (column split) + v4 RED ----
        for (int ss = wrp; ss < 2 * nseg_cur; ss += ETHREADS / 32) {
            int s = ss >> 1, half = ss & 1;
            int a0 = segs_c[s], a1 = segs_c[s + 1];
            int cbase = half ? 13 : 0;
            int ccnt  = half ? 12 : 13;
            if (lane < ccnt) {
                int c4 = cbase + lane;
                float4 acc = make_float4(0.0f, 0.0f, 0.0f, 0.0f);
                for (int ee = a0; ee < a1; ee++) {
                    int rr = fwd_c[ee];
                    float4 v = *reinterpret_cast<const float4*>(xs_c + rr * 100 + 4 * c4);
                    acc.x += v.x; acc.y += v.y; acc.z += v.z; acc.w += v.w;
                }
                red_add_v4(out + (size_t)mdc[a0].y * HID + 4 * c4, acc);
            }
        }
        __syncthreads();              // readers done before buffer reuse
        rot = (rot + 1) % 3;
        par ^= 1;
    }
}

// ---------------- host launcher ----------------
extern "C" void kernel_launch(void* const* d_in, const int* in_sizes, int n_in,
                              void* d_out, int out_size) {
    const float* node_emb = (const float*)d_in[0];
    const float* w1    = (const float*)d_in[1];
    const float* root1 = (const float*)d_in[2];
    const float* bias1 = (const float*)d_in[3];
    const float* w2    = (const float*)d_in[4];
    const float* root2 = (const float*)d_in[5];
    const float* bias2 = (const float*)d_in[6];
    const int*   eidx  = (const int*)d_in[7];
    const int*   etyp  = (const int*)d_in[8];
    float* out = (float*)d_out;

    int N = in_sizes[0] / HID;
    int E = in_sizes[8];
    if (N > MAXN) N = MAXN;
    int ntiles = (E + ETILE - 1) / ETILE;
    int Epad = ntiles * ETILE;
    if (Epad > MAXE) { Epad = MAXE; ntiles = Epad / ETILE; }

    float* h1 = nullptr;
    cudaGetSymbolAddress((void**)&h1, g_h1);

    const int EDGE_SMEM = (NREL * WSTRIDE + 2 * XROWS * 100) * 4   // ws + xs0/xs1
                        + 3 * ETILE * 16                            // meta x3
                        + (6 * ETILE + 2 * ETILE                    // sinv/fwd/srl + ssc
                           + 2 * (ETILE + 1) + 2 * 64               // segs + pp
                           + 48 + 48 + 16) * 4;
    const int INIT_SMEM = (GROWS * 101 + HID * HID) * 4;
    cudaFuncSetAttribute(k_edge, cudaFuncAttributeMaxDynamicSharedMemorySize, EDGE_SMEM);
    cudaFuncSetAttribute(k_init, cudaFuncAttributeMaxDynamicSharedMemorySize, INIT_SMEM);
    cudaFuncSetAttribute(k_pre,  cudaFuncAttributeMaxDynamicSharedMemorySize, INIT_SMEM);

    int RN = NREL * N;
    int nb = (N + 1023) / 1024;      // 98 blocks, all resident
    int init_grid = (N + GROWS - 1) / GROWS;
    int cnt_blocks = (E + GTHREADS - 1) / GTHREADS;
    const int EDGE_GRID = 148;

    // launch 0: fused count + layer-1 init (h1 = emb @ root1 + bias1)
    k_pre<<<cnt_blocks + init_grid, GTHREADS, INIT_SMEM>>>(
        eidx, etyp, E, N, node_emb, root1, bias1, h1, cnt_blocks);
    // launch 1: dst-histogram scan
    k_scan<<<nb, 1024>>>(N);
    // launch 2: dst-sorted edge scatter
    k_scatter<<<(E + 255) / 256, 256>>>(eidx, etyp, E, N);
    // launch 3 (profiled): layer-1 edge aggregation into h1
    k_edge<<<EDGE_GRID, ETHREADS, EDGE_SMEM>>>(node_emb, w1, h1, ntiles, 0);
    // launch 4: layer-2 init (out = relu(h1) @ root2 + bias2)
    k_init<<<init_grid, GTHREADS, INIT_SMEM>>>(h1, root2, bias2, out, N, 1);
    // launch 5: layer-2 edge aggregation into out
    k_edge<<<EDGE_GRID, ETHREADS, EDGE_SMEM>>>(h1, w2, out, ntiles, 1);
    // launch 6: restore buffer invariants
    k_cleanup<<<(RN + 255) / 256, 256>>>(N, RN, E, Epad);
}

// round 16
// speedup vs baseline: 1.3928x; 1.0088x over previous
#include <cuda_runtime.h>
#include <cstdint>

#define HID      100
#define NREL     16
#define NBLK     5
#define CB       20
#define MAXN     100000
#define MAXRN    (NREL * MAXN)
#define MAXE     1600128
#define WSTRIDE  2004         // per-relation weight stride (2000 used + 4 pad)
#define ETILE    96           // segments per tile
#define ETHREADS 480
#define XROWS    97           // 96 rows + scratch row for dummy pair halves

// ---------------- scratch (device globals; zero-initialized) ----------------
// Invariant at entry: g_cnt all zero (static init + k_cleanup).
__device__ int                g_cnt[MAXRN];        // per-key edge counts
__device__ int                g_cursor[MAXRN];     // per-key edge offsets (scatter cursors)
__device__ unsigned long long g_part[2048];        // scan partials (cnt | flag<<32)
__device__ int                g_esrc[MAXE];        // key-sorted edge srcs
__device__ int4               g_seg[MAXRN + 128];  // {edge_start, edge_end, dst, rel}
__device__ int                g_nseg[2];           // [0]=nseg, [1]=ntiles
__device__ float              g_h1[MAXN * HID];    // layer-1 output (pre-relu)

// ---------------- helpers ----------------
__device__ __forceinline__ uint32_t smaddr(const void* p) {
    return (uint32_t)__cvta_generic_to_shared(p);
}
__device__ __forceinline__ void cpa16(uint32_t s, const void* g) {
    asm volatile("cp.async.cg.shared.global [%0], [%1], 16;" :: "r"(s), "l"(g));
}
#define CPA_COMMIT() asm volatile("cp.async.commit_group;" ::: "memory")
#define CPA_WAIT0()  asm volatile("cp.async.wait_group 0;" ::: "memory")

__device__ __forceinline__ void red_add_v4(float* gptr, float4 v) {
    asm volatile("red.global.add.v4.f32 [%0], {%1, %2, %3, %4};"
                 :: "l"(gptr), "f"(v.x), "f"(v.y), "f"(v.z), "f"(v.w) : "memory");
}

// ---------------- dense init body: out = (relu?x) @ root + bias ----------------
#define GROWS 80
#define GTHREADS 256
__device__ __forceinline__ void init_body(const float* __restrict__ x,
                                          const float* __restrict__ root,
                                          const float* __restrict__ bias,
                                          float* __restrict__ out,
                                          int N, int do_relu, int rowbase,
                                          float* sm) {
    float* xs = sm;                   // 80 * 101
    float* rs = sm + GROWS * 101;     // 100 * 100
    int t = threadIdx.x;

    for (int i = t; i < HID * HID; i += GTHREADS) rs[i] = root[i];
    for (int i = t; i < GROWS * HID; i += GTHREADS) {
        int rr = i / HID, c = i - rr * HID;
        int row = rowbase + rr;
        float v = (row < N) ? x[(size_t)row * HID + c] : 0.0f;
        if (do_relu) v = fmaxf(v, 0.0f);
        xs[rr * 101 + c] = v;
    }
    __syncthreads();
    if (t >= 250) return;

    int q = t % 25;
    int rg = t / 25;
    float4 b4 = *reinterpret_cast<const float4*>(bias + 4 * q);
    float acc[8][4];
#pragma unroll
    for (int i = 0; i < 8; i++) {
        acc[i][0] = b4.x; acc[i][1] = b4.y; acc[i][2] = b4.z; acc[i][3] = b4.w;
    }
#pragma unroll 4
    for (int k = 0; k < HID; k++) {
        float4 r4 = *reinterpret_cast<const float4*>(rs + k * HID + 4 * q);
#pragma unroll
        for (int i = 0; i < 8; i++) {
            float xv = xs[(rg * 8 + i) * 101 + k];
            acc[i][0] = fmaf(xv, r4.x, acc[i][0]);
            acc[i][1] = fmaf(xv, r4.y, acc[i][1]);
            acc[i][2] = fmaf(xv, r4.z, acc[i][2]);
            acc[i][3] = fmaf(xv, r4.w, acc[i][3]);
        }
    }
#pragma unroll
    for (int i = 0; i < 8; i++) {
        int row = rowbase + rg * 8 + i;
        if (row < N) {
            float4 o;
            o.x = acc[i][0]; o.y = acc[i][1]; o.z = acc[i][2]; o.w = acc[i][3];
            *reinterpret_cast<float4*>(out + (size_t)row * HID + 4 * q) = o;
        }
    }
}

// ---------------- launch 0: fused key-count + layer-1 init ----------------
__global__ __launch_bounds__(GTHREADS)
void k_pre(const int* __restrict__ eidx, const int* __restrict__ etyp, int E, int N,
           const float* __restrict__ emb, const float* __restrict__ root1,
           const float* __restrict__ bias1, float* __restrict__ h1, int cntBlocks) {
    extern __shared__ float sm_i[];
    if ((int)blockIdx.x < cntBlocks) {
        int e = blockIdx.x * GTHREADS + threadIdx.x;
        if (e < E) {
            int dst = eidx[E + e];
            int rel = etyp[e];
            atomicAdd(&g_cnt[dst * NREL + rel], 1);
        }
    } else {
        int bid = blockIdx.x - cntBlocks;
        init_body(emb, root1, bias1, h1, N, 0, bid * GROWS, sm_i);
    }
}

__global__ __launch_bounds__(GTHREADS)
void k_init(const float* __restrict__ x, const float* __restrict__ root,
            const float* __restrict__ bias, float* __restrict__ out,
            int N, int do_relu) {
    extern __shared__ float sm_i[];
    init_body(x, root, bias, out, N, do_relu, blockIdx.x * GROWS, sm_i);
}

// ---------- 3-pass scan over RN keys of (cnt, nonempty-flag) packed in u64 ----------
__global__ void k_scan1(int RN) {
    __shared__ unsigned long long sh[1024];
    int t = threadIdx.x;
    int i = blockIdx.x * 1024 + t;
    unsigned long long v = 0;
    if (i < RN) {
        unsigned c = (unsigned)g_cnt[i];
        v = (unsigned long long)c | ((unsigned long long)(c > 0) << 32);
    }
    sh[t] = v;
    __syncthreads();
    for (int off = 512; off > 0; off >>= 1) {
        if (t < off) sh[t] += sh[t + off];
        __syncthreads();
    }
    if (t == 0) g_part[blockIdx.x] = sh[0];
}

__global__ void k_scan2(int nb) {       // 1 block, loops with carry
    __shared__ unsigned long long sh[1024];
    __shared__ unsigned long long s_carry;
    int t = threadIdx.x;
    if (t == 0) s_carry = 0;
    __syncthreads();
    for (int base = 0; base < nb; base += 1024) {
        int idx = base + t;
        unsigned long long v = (idx < nb) ? g_part[idx] : 0ull;
        sh[t] = v;
        __syncthreads();
        for (int off = 1; off < 1024; off <<= 1) {
            unsigned long long u = (t >= off) ? sh[t - off] : 0ull;
            __syncthreads();
            sh[t] += u;
            __syncthreads();
        }
        unsigned long long carry = s_carry;
        if (idx < nb) g_part[idx] = carry + sh[t] - v;   // exclusive
        __syncthreads();
        if (t == 1023) s_carry = carry + sh[1023];
        __syncthreads();
    }
}

// scan3 + segment-table build
__global__ void k_scan3(int RN) {
    __shared__ unsigned long long sh[1024];
    int t = threadIdx.x;
    int i = blockIdx.x * 1024 + t;
    unsigned c = 0;
    if (i < RN) c = (unsigned)g_cnt[i];
    unsigned long long v = (unsigned long long)c | ((unsigned long long)(c > 0) << 32);
    sh[t] = v;
    __syncthreads();
    for (int off = 1; off < 1024; off <<= 1) {
        unsigned long long u = (t >= off) ? sh[t - off] : 0ull;
        __syncthreads();
        sh[t] += u;
        __syncthreads();
    }
    if (i < RN) {
        unsigned long long excl = g_part[blockIdx.x] + sh[t] - v;
        int keyoff   = (int)(unsigned)excl;
        int flagrank = (int)(unsigned)(excl >> 32);
        g_cursor[i] = keyoff;
        if (c > 0)
            g_seg[flagrank] = make_int4(keyoff, keyoff + (int)c, i / NREL, i % NREL);
        if (i == RN - 1)
            g_nseg[0] = flagrank + (c > 0 ? 1 : 0);
    }
}

// scatter srcs into key-sorted order; last block pads the segment table
__global__ void k_scatter(const int* __restrict__ eidx, const int* __restrict__ etyp,
                          int E, int N, int scatBlocks) {
    if ((int)blockIdx.x < scatBlocks) {
        int e = blockIdx.x * blockDim.x + threadIdx.x;
        if (e >= E) return;
        int key = eidx[E + e] * NREL + etyp[e];
        int p = atomicAdd(&g_cursor[key], 1);
        g_esrc[p] = eidx[e];
    } else {
        int nseg = *(volatile int*)&g_nseg[0];
        int ntiles = (nseg + ETILE - 1) / ETILE;
        int j = nseg + threadIdx.x;
        if (j < ntiles * ETILE)
            g_seg[j] = make_int4(E, E, N - 1, 0);   // empty seg, safe dst
        if (threadIdx.x == 0) g_nseg[1] = ntiles;
    }
}

__global__ void k_cleanup(int RN) {
    int i = blockIdx.x * blockDim.x + threadIdx.x;
    if (i < RN) g_cnt[i] = 0;
}

// ---------------- edge kernel: tiles of 96 (dst,rel)-SEGMENTS ----------------
// meta int4 {start, end, dst, rel}, key-sorted -> same-dst segs adjacent.
// Per tile: rel counting-sort (pairs for weight reuse) + dst-ballot;
// GATHER: thread (b,j) sums its segment's x rows (relu folded) in registers,
// writes rel-sorted row j to xs; pair transform in place; dst-reduce + v4 RED.
__device__ __forceinline__ void sort_tile96(const int4* md, int* sinv, int* fwd,
                                            int* srl, float* ssc, int* segs, int* pp,
                                            int* scnt, int* sbase, int* swx,
                                            int t, int lane, int wrp) {
    int myrel = 0, myrank = 0;
    if (t < ETILE) {
        myrel = md[t].w;
        unsigned m = __match_any_sync(0xFFFFFFFFu, myrel);
        myrank = __popc(m & ((1u << lane) - 1u));
        if ((int)(__ffs(m) - 1) == lane) scnt[wrp * 16 + myrel] = __popc(m);
    } else if (t < 2 * ETILE) {
        int p = t - ETILE;
        bool head = (p == 0) || (md[p - 1].z != md[p].z);
        unsigned bal = __ballot_sync(0xFFFFFFFFu, head);
        if (lane == 0) swx[wrp - 3] = __popc(bal);
    }
    __syncthreads();
    if (t < 16) {
        int c0 = scnt[t], c1 = scnt[16 + t], c2 = scnt[32 + t];
        int tot = c0 + c1 + c2;
        int run = tot;
#pragma unroll
        for (int d = 1; d < 16; d <<= 1) {
            int v = __shfl_up_sync(0xFFFFu, run, d);
            if (lane >= d) run += v;
        }
        int off = run - tot;
        sbase[t]      = off;
        sbase[16 + t] = off + c0;
        sbase[32 + t] = off + c0 + c1;
        int pcnt = (tot + 1) >> 1;
        int runp = pcnt;
#pragma unroll
        for (int d = 1; d < 16; d <<= 1) {
            int v = __shfl_up_sync(0xFFFFu, runp, d);
            if (lane >= d) runp += v;
        }
        int poff = runp - pcnt;
        for (int j = 0; j < pcnt; j++)
            pp[poff + j] = (off + 2 * j) | ((2 * j + 1 < tot) ? 0x10000 : 0);
        if (t == 15) swx[7] = runp;   // npairs
    }
    if (t == 2 * ETILE) {
        int a = swx[0], b2 = swx[1], c = swx[2];
        int ns = a + b2 + c;
        swx[3] = 0; swx[4] = a; swx[5] = a + b2; swx[6] = ns;
        segs[ns] = ETILE;
    }
    __syncthreads();
    if (t < ETILE) {
        int pos = sbase[wrp * 16 + myrel] + myrank;
        sinv[pos] = t;
        fwd[t] = pos;
        srl[pos] = myrel;
        int cnt = md[t].y - md[t].x;
        ssc[pos] = (cnt > 0) ? 1.0f / (float)cnt : 0.0f;
    } else if (t < 2 * ETILE) {
        int p = t - ETILE;
        bool head = (p == 0) || (md[p - 1].z != md[p].z);
        unsigned bal = __ballot_sync(0xFFFFFFFFu, head);
        if (head) segs[swx[3 + (wrp - 3)] + __popc(bal & ((1u << lane) - 1u))] = p;
    } else if (t < 2 * ETILE + 48) {
        scnt[t - 2 * ETILE] = 0;
    }
    __syncthreads();
}

// gather: thread (b,j) sums segment sinv[j]'s x rows into registers, STS to row j
__device__ __forceinline__ void gather_tile(const float* __restrict__ x,
                                            const int4* md, const int* sinv,
                                            float* xs, int t, int do_relu) {
    int b = t / ETILE;
    int j = t - b * ETILE;
    int so = sinv[j];
    int4 m = md[so];
    float4 acc[5];
#pragma unroll
    for (int k = 0; k < 5; k++) acc[k] = make_float4(0.0f, 0.0f, 0.0f, 0.0f);
    for (int e = m.x; e < m.y; e++) {
        int src = __ldg(&g_esrc[e]);
        const float4* xg = reinterpret_cast<const float4*>(x + (size_t)src * HID + b * CB);
#pragma unroll
        for (int k = 0; k < 5; k++) {
            float4 v = __ldg(xg + k);
            if (do_relu) {
                v.x = fmaxf(v.x, 0.0f); v.y = fmaxf(v.y, 0.0f);
                v.z = fmaxf(v.z, 0.0f); v.w = fmaxf(v.w, 0.0f);
            }
            acc[k].x += v.x; acc[k].y += v.y; acc[k].z += v.z; acc[k].w += v.w;
        }
    }
    float4* d = reinterpret_cast<float4*>(xs + j * 100 + b * CB);
#pragma unroll
    for (int k = 0; k < 5; k++) d[k] = acc[k];
}

__global__ __launch_bounds__(ETHREADS)
void k_edge(const float* __restrict__ x, const float* __restrict__ w,
            float* __restrict__ out, int do_relu) {
    extern __shared__ float sm_e[];
    float* ws    = sm_e;                               // 16*2004
    float* xs0   = ws + NREL * WSTRIDE;                // 97*100
    float* xs1   = xs0 + XROWS * 100;                  // 97*100
    int4*  mds0  = (int4*)(xs1 + XROWS * 100);         // 3*96 int4
    int*   sinv0 = (int*)(mds0 + 3 * ETILE);
    int*   sinv1 = sinv0 + ETILE;
    int*   fwd0  = sinv1 + ETILE;
    int*   fwd1  = fwd0 + ETILE;
    int*   srl0  = fwd1 + ETILE;
    int*   srl1  = srl0 + ETILE;
    float* ssc0  = (float*)(srl1 + ETILE);
    float* ssc1  = ssc0 + ETILE;
    int*   segs0 = (int*)(ssc1 + ETILE);               // 97
    int*   segs1 = segs0 + ETILE + 1;                  // 97
    int*   pp0   = segs1 + ETILE + 1;                  // 64
    int*   pp1   = pp0 + 64;                           // 64
    int*   scnt  = pp1 + 64;                           // 48
    int*   sbase = scnt + 48;                          // 48
    int*   swx   = sbase + 48;                         // 16

    int t = threadIdx.x;
    int lane = t & 31;
    int wrp = t >> 5;

    for (int i = t; i < NREL * 2000; i += ETHREADS) {
        int r = i / 2000;
        ws[r * WSTRIDE + (i - r * 2000)] = w[i];
    }
    if (t < 48) scnt[t] = 0;

    int ntiles = *(volatile int*)&g_nseg[1];
    int grid = gridDim.x;
    int tile0 = blockIdx.x;
    if (tile0 >= ntiles) return;   // uniform per block

    // ---- preloop: meta(t0) -> sort -> gather x(t0); prefetch meta(t0+g) ----
    if (t < ETILE) cpa16(smaddr(mds0 + t), &g_seg[(size_t)tile0 * ETILE + t]);
    CPA_COMMIT();
    CPA_WAIT0();
    __syncthreads();
    sort_tile96(mds0, sinv0, fwd0, srl0, ssc0, segs0, pp0, scnt, sbase, swx, t, lane, wrp);
    gather_tile(x, mds0, sinv0, xs0, t, do_relu);
    if (tile0 + grid < ntiles && t < ETILE)
        cpa16(smaddr(mds0 + ETILE + t), &g_seg[(size_t)(tile0 + grid) * ETILE + t]);
    CPA_COMMIT();
    __syncthreads();               // gather(t0) complete

    int par = 0, rot = 0;
    for (int tile = tile0; tile < ntiles; tile += grid) {
        CPA_WAIT0();               // meta(tile+g) arrived
        __syncthreads();           // sync1: prev phase3 done; snapshot safe
        int nseg_cur   = swx[6];
        int npairs_cur = swx[7];
        int nxt = tile + grid;

        float* xs_c  = par ? xs1 : xs0;
        float* xs_n  = par ? xs0 : xs1;
        int*   sinv_n = par ? sinv0 : sinv1;
        int*   fwd_c = par ? fwd1 : fwd0;
        int*   fwd_n = par ? fwd0 : fwd1;
        int*   srl_c = par ? srl1 : srl0;
        int*   srl_n = par ? srl0 : srl1;
        float* ssc_c = par ? ssc1 : ssc0;
        float* ssc_n = par ? ssc0 : ssc1;
        int*   segs_c = par ? segs1 : segs0;
        int*   segs_n = par ? segs0 : segs1;
        int*   pp_c  = par ? pp1 : pp0;
        int*   pp_n  = par ? pp0 : pp1;
        const int4* mdc = mds0 + rot * ETILE;

        // ---- sort + gather tile (nxt) ----
        if (nxt < ntiles) {
            const int4* mdn = mds0 + ((rot + 1) % 3) * ETILE;
            sort_tile96(mdn, sinv_n, fwd_n, srl_n, ssc_n, segs_n, pp_n,
                        scnt, sbase, swx, t, lane, wrp);
            gather_tile(x, mdn, sinv_n, xs_n, t, do_relu);
        }

        // ---- phase 2: pair transform on xs_c, in place ----
        if (t < 320) {
            int p = t & 63;
            if (p < npairs_cur) {
                int b = t >> 6;
                int v = pp_c[p];
                int r0 = v & 0xffff;
                int val1 = v >> 16;
                int rr1 = r0 + val1;
                int wr1 = val1 ? (r0 + 1) : 96;
                int rel = srl_c[r0];
                float sc0 = ssc_c[r0];
                float sc1 = val1 ? ssc_c[r0 + 1] : 0.0f;

                float xv0[CB], xv1[CB];
                const float4* x0 = reinterpret_cast<const float4*>(xs_c + r0 * 100 + b * CB);
                const float4* x1 = reinterpret_cast<const float4*>(xs_c + rr1 * 100 + b * CB);
#pragma unroll
                for (int k = 0; k < 5; k++) {
                    float4 a = x0[k], bb = x1[k];
                    xv0[4 * k] = a.x; xv0[4 * k + 1] = a.y; xv0[4 * k + 2] = a.z; xv0[4 * k + 3] = a.w;
                    xv1[4 * k] = bb.x; xv1[4 * k + 1] = bb.y; xv1[4 * k + 2] = bb.z; xv1[4 * k + 3] = bb.w;
                }
                const float* wb = ws + rel * WSTRIDE + b * (CB * CB);
                float a0[CB], a1[CB];
#pragma unroll
                for (int d = 0; d < CB; d++) { a0[d] = 0.0f; a1[d] = 0.0f; }
#pragma unroll
                for (int c = 0; c < CB; c++) {
                    float c0 = xv0[c], c1 = xv1[c];
                    const float4* w4 = reinterpret_cast<const float4*>(wb + c * CB);
#pragma unroll
                    for (int d4 = 0; d4 < 5; d4++) {
                        float4 wv = w4[d4];
                        a0[4 * d4]     = fmaf(c0, wv.x, a0[4 * d4]);
                        a0[4 * d4 + 1] = fmaf(c0, wv.y, a0[4 * d4 + 1]);
                        a0[4 * d4 + 2] = fmaf(c0, wv.z, a0[4 * d4 + 2]);
                        a0[4 * d4 + 3] = fmaf(c0, wv.w, a0[4 * d4 + 3]);
                        a1[4 * d4]     = fmaf(c1, wv.x, a1[4 * d4]);
                        a1[4 * d4 + 1] = fmaf(c1, wv.y, a1[4 * d4 + 1]);
                        a1[4 * d4 + 2] = fmaf(c1, wv.z, a1[4 * d4 + 2]);
                        a1[4 * d4 + 3] = fmaf(c1, wv.w, a1[4 * d4 + 3]);
                    }
                }
                float4* w0 = reinterpret_cast<float4*>(xs_c + r0 * 100 + b * CB);
                float4* w1p = reinterpret_cast<float4*>(xs_c + wr1 * 100 + b * CB);
#pragma unroll
                for (int d4 = 0; d4 < 5; d4++) {
                    float4 o0, o1;
                    o0.x = a0[4 * d4] * sc0;     o0.y = a0[4 * d4 + 1] * sc0;
                    o0.z = a0[4 * d4 + 2] * sc0; o0.w = a0[4 * d4 + 3] * sc0;
                    o1.x = a1[4 * d4] * sc1;     o1.y = a1[4 * d4 + 1] * sc1;
                    o1.z = a1[4 * d4 + 2] * sc1; o1.w = a1[4 * d4 + 3] * sc1;
                    w0[d4] = o0;
                    w1p[d4] = o1;
                }
            }
        }
        __syncthreads();           // syncB: transform(t) + gather(t+1) complete

        // ---- phase 3: 2 warps per dst-run (column split) + v4 RED ----
        for (int ss = wrp; ss < 2 * nseg_cur; ss += ETHREADS / 32) {
            int s = ss >> 1, half = ss & 1;
            int a0 = segs_c[s], a1 = segs_c[s + 1];
            int cbase = half ? 13 : 0;
            int ccnt  = half ? 12 : 13;
            if (lane < ccnt) {
                int c4 = cbase + lane;
                float4 acc = make_float4(0.0f, 0.0f, 0.0f, 0.0f);
                for (int ee = a0; ee < a1; ee++) {
                    int rr = fwd_c[ee];
                    float4 v = *reinterpret_cast<const float4*>(xs_c + rr * 100 + 4 * c4);
                    acc.x += v.x; acc.y += v.y; acc.z += v.z; acc.w += v.w;
                }
                red_add_v4(out + (size_t)mdc[a0].z * HID + 4 * c4, acc);
            }
        }
        // ---- prefetch meta(tile + 2*grid) ----
        if (tile + 2 * grid < ntiles && t < ETILE)
            cpa16(smaddr(mds0 + ((rot + 2) % 3) * ETILE + t),
                  &g_seg[(size_t)(tile + 2 * grid) * ETILE + t]);
        CPA_COMMIT();
        rot = (rot + 1) % 3;
        par ^= 1;
    }
}

// ---------------- host launcher ----------------
extern "C" void kernel_launch(void* const* d_in, const int* in_sizes, int n_in,
                              void* d_out, int out_size) {
    const float* node_emb = (const float*)d_in[0];
    const float* w1    = (const float*)d_in[1];
    const float* root1 = (const float*)d_in[2];
    const float* bias1 = (const float*)d_in[3];
    const float* w2    = (const float*)d_in[4];
    const float* root2 = (const float*)d_in[5];
    const float* bias2 = (const float*)d_in[6];
    const int*   eidx  = (const int*)d_in[7];
    const int*   etyp  = (const int*)d_in[8];
    float* out = (float*)d_out;

    int N = in_sizes[0] / HID;
    int E = in_sizes[8];
    if (N > MAXN) N = MAXN;
    if (E > MAXE) E = MAXE;

    float* h1 = nullptr;
    cudaGetSymbolAddress((void**)&h1, g_h1);

    const int EDGE_SMEM = (NREL * WSTRIDE + 2 * XROWS * 100) * 4
                        + 3 * ETILE * 16
                        + (6 * ETILE + 2 * ETILE
                           + 2 * (ETILE + 1) + 2 * 64
                           + 48 + 48 + 16) * 4;
    const int INIT_SMEM = (GROWS * 101 + HID * HID) * 4;
    cudaFuncSetAttribute(k_edge, cudaFuncAttributeMaxDynamicSharedMemorySize, EDGE_SMEM);
    cudaFuncSetAttribute(k_init, cudaFuncAttributeMaxDynamicSharedMemorySize, INIT_SMEM);
    cudaFuncSetAttribute(k_pre,  cudaFuncAttributeMaxDynamicSharedMemorySize, INIT_SMEM);

    int RN = N * NREL;
    int nb = (RN + 1023) / 1024;     // <= 1563
    int init_grid = (N + GROWS - 1) / GROWS;
    int cnt_blocks = (E + GTHREADS - 1) / GTHREADS;
    int scat_blocks = (E + 255) / 256;
    const int EDGE_GRID = 148;

    // 0: fused key-count + layer-1 root GEMM
    k_pre<<<cnt_blocks + init_grid, GTHREADS, INIT_SMEM>>>(
        eidx, etyp, E, N, node_emb, root1, bias1, h1, cnt_blocks);
    // 1-3: 3-pass scan (cnt + nonempty flag) + segment-table build
    k_scan1<<<nb, 1024>>>(RN);
    k_scan2<<<1, 1024>>>(nb);
    k_scan3<<<nb, 1024>>>(RN);
    // 4: key-sorted src scatter + segment padding (extra block)
    k_scatter<<<scat_blocks + 1, 256>>>(eidx, etyp, E, N, scat_blocks);
    // 5: layer-1 segment aggregation + transform into h1
    k_edge<<<EDGE_GRID, ETHREADS, EDGE_SMEM>>>(node_emb, w1, h1, 0);
    // 6: layer-2 root GEMM (out = relu(h1) @ root2 + bias2)
    k_init<<<init_grid, GTHREADS, INIT_SMEM>>>(h1, root2, bias2, out, N, 1);
    // 7: layer-2 segment aggregation + transform into out (relu in gather)
    k_edge<<<EDGE_GRID, ETHREADS, EDGE_SMEM>>>(h1, w2, out, 1);
    // 8: restore invariants
    k_cleanup<<<(RN + 255) / 256, 256>>>(RN);
}